// round 15
// baseline (speedup 1.0000x reference)
#include <cuda_runtime.h>
#include <cuda_fp16.h>
#include <cstdint>

// ---------------- problem constants ----------------
#define B_    16
#define T_    8
#define CIN   2048
#define CI    512
#define HF    14
#define HW    196
#define NROI  512
#define M1    4608          // NROI*9
#define KFEAT 4608          // CI*9
#define NPART 8             // split-K parts for gemm2

// ---------------- scratch (static device memory) ----------------
__device__ __half d_roisH[(size_t)M1 * CIN];
__device__ __half d_wH[(size_t)CI * CIN];
__device__ __half d_rwH[(size_t)CI * KFEAT];       // re_w transposed+permuted [n][bin*512+o]
__device__ __half d_featsH[(size_t)NROI * KFEAT];  // [roi][bin*512+o]
__device__ float d_regpart[(size_t)NPART * NROI * CI];
__device__ float d_snb[64 * CI];
__device__ float d_objf[32 * CI];
__device__ float d_h1[32 * CI];
__device__ float d_g1[16 * CI];
__device__ int2  d_tap[NROI * 9 * 16];   // {byte-offset into 197-float row, weight bits}

// ---------------- PTX helpers ----------------
__device__ __forceinline__ uint32_t sm_u32(const void* p) {
    return (uint32_t)__cvta_generic_to_shared(p);
}
__device__ __forceinline__ void cpa16(uint32_t dst, const void* src) {
    asm volatile("cp.async.cg.shared.global [%0], [%1], 16;\n" :: "r"(dst), "l"(src));
}
__device__ __forceinline__ void cpa_commit() {
    asm volatile("cp.async.commit_group;\n" ::: "memory");
}
__device__ __forceinline__ void cpa_wait3() {
    asm volatile("cp.async.wait_group 3;\n" ::: "memory");
}
__device__ __forceinline__ void ldsm4(uint32_t* r, uint32_t addr) {
    asm volatile("ldmatrix.sync.aligned.m8n8.x4.shared.b16 {%0,%1,%2,%3}, [%4];"
                 : "=r"(r[0]), "=r"(r[1]), "=r"(r[2]), "=r"(r[3]) : "r"(addr));
}
__device__ __forceinline__ void mma16816h(float* c, const uint32_t* a, uint32_t b0, uint32_t b1) {
    asm volatile("mma.sync.aligned.m16n8k16.row.col.f32.f16.f16.f32 "
                 "{%0,%1,%2,%3},{%4,%5,%6,%7},{%8,%9},{%0,%1,%2,%3};"
                 : "+f"(c[0]), "+f"(c[1]), "+f"(c[2]), "+f"(c[3])
                 : "r"(a[0]), "r"(a[1]), "r"(a[2]), "r"(a[3]), "r"(b0), "r"(b1));
}

// ============================================================
// K0: merged prep: [0] build_table (2), convw (4096), convrw (2304)
// ============================================================
#define PREP_BT   2
#define PREP_CW   (CI * CIN / 256)          // 4096
#define PREP_CRW  (16 * 16 * 9)             // 2304
__global__ __launch_bounds__(256) void prep_kernel(
    const float* __restrict__ boxes,
    const float* __restrict__ conv5_w,
    const float* __restrict__ re_w)
{
    int bid = blockIdx.x;
    if (bid < PREP_BT) {
        int roi = bid * 256 + threadIdx.x;
        if (roi >= NROI) return;
        float cx = boxes[roi * 4 + 0], cy = boxes[roi * 4 + 1];
        float w  = boxes[roi * 4 + 2], h  = boxes[roi * 4 + 3];
        const float s = 14.0f / 224.0f;
        float x1 = (cx - 0.5f * w) * 224.0f * s;
        float y1 = (cy - 0.5f * h) * 224.0f * s;
        float x2 = (cx + 0.5f * w) * 224.0f * s;
        float y2 = (cy + 0.5f * h) * 224.0f * s;
        float rw = fmaxf(x2 - x1, 1.0f), rh = fmaxf(y2 - y1, 1.0f);
        float bw = rw / 3.0f, bh = rh / 3.0f;
        float ys[6], xs[6];
#pragma unroll
        for (int p = 0; p < 3; ++p)
#pragma unroll
            for (int i = 0; i < 2; ++i) {
                ys[p * 2 + i] = y1 + p * bh + (i + 0.5f) * bh * 0.5f;
                xs[p * 2 + i] = x1 + p * bw + (i + 0.5f) * bw * 0.5f;
            }
#pragma unroll
        for (int ph = 0; ph < 3; ++ph)
#pragma unroll
            for (int pw = 0; pw < 3; ++pw) {
                int bin = ph * 3 + pw;
#pragma unroll
                for (int iy = 0; iy < 2; ++iy)
#pragma unroll
                    for (int ix = 0; ix < 2; ++ix) {
                        int smp = iy * 2 + ix;
                        float yy = ys[ph * 2 + iy];
                        float xx = xs[pw * 2 + ix];
                        bool valid = (yy > -1.0f) && (yy < 14.0f) && (xx > -1.0f) && (xx < 14.0f);
                        float y = fminf(fmaxf(yy, 0.0f), 13.0f);
                        float x = fminf(fmaxf(xx, 0.0f), 13.0f);
                        int y0 = (int)floorf(y), x0 = (int)floorf(x);
                        int y1i = min(y0 + 1, 13), x1i = min(x0 + 1, 13);
                        float ly = y - (float)y0, lx = x - (float)x0;
                        float hy = 1.0f - ly, hx = 1.0f - lx;
                        float q = valid ? 0.25f : 0.0f;
                        int base = (roi * 9 + bin) * 16 + smp * 4;
                        d_tap[base + 0] = make_int2((y0 * HF + x0) * 4,   __float_as_int(hy * hx * q));
                        d_tap[base + 1] = make_int2((y0 * HF + x1i) * 4,  __float_as_int(hy * lx * q));
                        d_tap[base + 2] = make_int2((y1i * HF + x0) * 4,  __float_as_int(ly * hx * q));
                        d_tap[base + 3] = make_int2((y1i * HF + x1i) * 4, __float_as_int(ly * lx * q));
                    }
            }
    } else if (bid < PREP_BT + PREP_CW) {
        int i = (bid - PREP_BT) * 256 + threadIdx.x;
        d_wH[i] = __float2half_rn(conv5_w[i]);
    } else {
        __shared__ float t[32][33];
        int cb = bid - PREP_BT - PREP_CW;
        int bin = cb / 256;
        int rem = cb - bin * 256;
        int o0 = (rem >> 4) * 32, n0 = (rem & 15) * 32;
        int tx = threadIdx.x & 31, ty = threadIdx.x >> 5;
        for (int r = ty; r < 32; r += 8)
            t[r][tx] = re_w[((size_t)((o0 + r) * 9 + bin)) * 512 + n0 + tx];
        __syncthreads();
        for (int r = ty; r < 32; r += 8) {
            size_t off = (size_t)(n0 + r) * KFEAT + bin * 512 + o0 + tx;
            d_rwH[off] = __float2half_rn(t[tx][r]);
        }
    }
}

// ============================================================
// K2: pooling in 2048-ch space -> fp16
// 8 chunks of 32 channels per block, 2 smem buffers (dynamic),
// register-staged LDG double-buffering; int4 (2-tap) LDS.128 loads
// ============================================================
#define PCHUNKS 8
#define PLDG    6
#define PBUF_E  (32 * 197)
#define POOL_SMEM (2 * PBUF_E * 4 + 576 * 8)
__global__ __launch_bounds__(288) void pool_kernel(const float* __restrict__ x) {
    extern __shared__ float psm[];
    float* pl0 = psm;
    float* pl1 = psm + PBUF_E;
    int2*  taps = (int2*)(psm + 2 * PBUF_E);

    int bt = blockIdx.y;
    int tid = threadIdx.x, lane = tid & 31, wid = tid >> 5;
    int cbase = blockIdx.x * (32 * PCHUNKS);

    size_t xbase = ((size_t)(bt >> 3) * CIN + cbase) * (size_t)(T_ * HW) + (size_t)(bt & 7) * HW;

    for (int i = tid; i < 576; i += 288) taps[i] = d_tap[bt * 576 + i];

    float4 v[PLDG];
    auto ldgc = [&](int c) {
#pragma unroll
        for (int q = 0; q < PLDG; ++q) {
            int i = tid + q * 288;
            if (i < 1568) {
                int ch = i / 49, p = i - ch * 49;
                v[q] = *(const float4*)(x + xbase + (size_t)(c * 32 + ch) * (T_ * HW) + p * 4);
            }
        }
    };
    auto stsc = [&](float* buf) {
#pragma unroll
        for (int q = 0; q < PLDG; ++q) {
            int i = tid + q * 288;
            if (i < 1568) {
                int ch = i / 49, p = i - ch * 49;
                float* d = buf + ch * 197 + p * 4;
                d[0] = v[q].x; d[1] = v[q].y; d[2] = v[q].z; d[3] = v[q].w;
            }
        }
    };

    ldgc(0);
    stsc(pl0);
    __syncthreads();

#pragma unroll
    for (int c = 0; c < PCHUNKS; ++c) {
        if (c + 1 < PCHUNKS) ldgc(c + 1);

        const char* bp = (const char*)((c & 1) ? (pl1 + lane * 197) : (pl0 + lane * 197));
#pragma unroll
        for (int j = 0; j < 4; ++j) {
            int e = wid + 9 * j;
            const int4* tp4 = (const int4*)&taps[e * 16];   // 2 taps per LDS.128
            float a = 0.0f;
#pragma unroll
            for (int t = 0; t < 8; ++t) {
                int4 q = tp4[t];
                a += __int_as_float(q.y) * *(const float*)(bp + q.x);
                a += __int_as_float(q.w) * *(const float*)(bp + q.z);
            }
            size_t off = (size_t)(bt * 36 + e) * CIN + cbase + c * 32 + lane;
            d_roisH[off] = __float2half_rn(a);
        }

        if (c + 1 < PCHUNKS) {
            stsc(((c + 1) & 1) ? pl1 : pl0);
            __syncthreads();
        }
    }
}

// ============================================================
// GEMM core: 64x128 tile, 256 threads (8 warps, 2x4 grid, warp 32x32),
// single-pass fp16, 5-stage cp.async -> 2 CTAs/SM co-residency
// ============================================================
#define KT     32
#define SROW   40
#define AROWS  64
#define BROWS  128
#define STAGE_E ((AROWS + BROWS) * SROW)
#define NSTAGE 5
#define GSMEM_BYTES (NSTAGE * STAGE_E * 2)

__device__ __forceinline__ void gemm_core(
    const __half* __restrict__ gA, int lda,
    const __half* __restrict__ gB, int ldb,
    int bm, int bn, int kbase, int niter,
    __half* sm, float (&acc)[2][4][4])
{
    int tid = threadIdx.x, lane = tid & 31, wid = tid >> 5;
    int wm = wid >> 2, wn = wid & 3;

    auto ldg = [&](int t) {
        int s = t % NSTAGE;
        int k0 = kbase + t * KT;
        __half* base = sm + s * STAGE_E;
#pragma unroll
        for (int q = 0; q < 3; ++q) {
            int idx = tid + q * 256;
            int row = idx >> 2, c = idx & 3;
            __half* pd = base + row * SROW + c * 8;
            const __half* src = (row < AROWS)
                ? gA + (size_t)(bm + row) * lda + k0 + c * 8
                : gB + (size_t)(bn + row - AROWS) * ldb + k0 + c * 8;
            cpa16(sm_u32(pd), src);
        }
    };

    int ar  = wm * 32 + (lane & 15);
    int ac8 = (lane >> 4) * 8;
    int br  = wn * 32 + (lane & 7) + ((lane >> 4) << 3);
    int bc8 = ((lane >> 3) & 1) * 8;

#pragma unroll
    for (int s = 0; s < 4; ++s) {
        if (s < niter) ldg(s);
        cpa_commit();
    }

#pragma unroll 1
    for (int t = 0; t < niter; ++t) {
        cpa_wait3();
        __syncthreads();
        if (t + 4 < niter) ldg(t + 4);
        cpa_commit();

        __half* base = sm + (t % NSTAGE) * STAGE_E;
        const __half* pA = base;
        const __half* pB = base + AROWS * SROW;

        uint32_t ah[2][2][4], bh[2][2][4];
#pragma unroll
        for (int ks = 0; ks < 2; ++ks) {
#pragma unroll
            for (int mt = 0; mt < 2; ++mt)
                ldsm4(ah[ks][mt], sm_u32(pA + (ar + mt * 16) * SROW + ks * 16 + ac8));
#pragma unroll
            for (int bt2 = 0; bt2 < 2; ++bt2)
                ldsm4(bh[ks][bt2], sm_u32(pB + (br + bt2 * 16) * SROW + ks * 16 + bc8));
        }
#pragma unroll
        for (int ks = 0; ks < 2; ++ks)
#pragma unroll
            for (int mt = 0; mt < 2; ++mt)
#pragma unroll
                for (int nt = 0; nt < 4; ++nt)
                    mma16816h(acc[mt][nt], ah[ks][mt],
                              bh[ks][nt >> 1][(nt & 1) * 2], bh[ks][nt >> 1][(nt & 1) * 2 + 1]);
    }
}

// ============================================================
// K4: GEMM1: feats = rois2048[4608,2048] x conv5_w[512,2048]^T
// ============================================================
__global__ __launch_bounds__(256) void gemm1k() {
    extern __shared__ __half sm[];
    int bm = blockIdx.y * 64, bn = blockIdx.x * 128;
    float acc[2][4][4];
#pragma unroll
    for (int a = 0; a < 2; ++a)
#pragma unroll
        for (int b = 0; b < 4; ++b)
#pragma unroll
            for (int c = 0; c < 4; ++c) acc[a][b][c] = 0.0f;

    gemm_core(d_roisH, CIN, d_wH, CIN, bm, bn, 0, CIN / KT, sm, acc);

    int lane = threadIdx.x & 31, wid = threadIdx.x >> 5;
    int wm = wid >> 2, wn = wid & 3;
    int mrow = wm * 32 + (lane >> 2);
    int ncol = wn * 32 + ((lane & 3) << 1);
#pragma unroll
    for (int mt = 0; mt < 2; ++mt)
#pragma unroll
        for (int nt = 0; nt < 4; ++nt) {
            float* c = acc[mt][nt];
            int n = bn + ncol + nt * 8;
#pragma unroll
            for (int half = 0; half < 2; ++half) {
                int m = bm + mrow + mt * 16 + half * 8;
                int roi = m / 9, bin = m - roi * 9;
                size_t off = (size_t)roi * KFEAT + bin * 512 + n;
                __half2 hp;
                hp.x = __float2half_rn(c[half * 2 + 0]);
                hp.y = __float2half_rn(c[half * 2 + 1]);
                *(__half2*)&d_featsH[off] = hp;
            }
        }
}

// ============================================================
// K5: GEMM2 (split-K=8): regpart = feats[512,4608] x rw[512,4608]^T
// ============================================================
__global__ __launch_bounds__(256) void gemm2k() {
    extern __shared__ __half sm[];
    int bm = blockIdx.y * 64, bn = blockIdx.x * 128;
    int part = blockIdx.z;
    float acc[2][4][4];
#pragma unroll
    for (int a = 0; a < 2; ++a)
#pragma unroll
        for (int b = 0; b < 4; ++b)
#pragma unroll
            for (int c = 0; c < 4; ++c) acc[a][b][c] = 0.0f;

    gemm_core(d_featsH, KFEAT, d_rwH, KFEAT,
              bm, bn, part * (KFEAT / NPART), (KFEAT / NPART) / KT, sm, acc);

    int lane = threadIdx.x & 31, wid = threadIdx.x >> 5;
    int wm = wid >> 2, wn = wid & 3;
    int mrow = wm * 32 + (lane >> 2);
    int ncol = wn * 32 + ((lane & 3) << 1);
    float* C = d_regpart + (size_t)part * NROI * CI;
#pragma unroll
    for (int mt = 0; mt < 2; ++mt)
#pragma unroll
        for (int nt = 0; nt < 4; ++nt) {
            float* c = acc[mt][nt];
            int n = bn + ncol + nt * 8;
#pragma unroll
            for (int half = 0; half < 2; ++half) {
                int m = bm + mrow + mt * 16 + half * 8;
                *(float2*)&C[(size_t)m * CI + n] = make_float2(c[half * 2], c[half * 2 + 1]);
            }
        }
}

// ============================================================
// K6: per-(b,nb): s = 0.125 * sum_t relu(bias + sum_p parts); labels
// ============================================================
__global__ void reduce_a(const float* __restrict__ re_b,
                         const int* __restrict__ cat,
                         float* __restrict__ out_labels) {
    int b = blockIdx.x, nb = blockIdx.y, j = threadIdx.x;
    float bias = re_b[j];
    float s = 0.0f;
#pragma unroll
    for (int t = 0; t < 8; ++t) {
        int r = (b * 8 + t) * 4 + nb;
        float v = bias;
#pragma unroll
        for (int p = 0; p < NPART; ++p)
            v += d_regpart[(size_t)p * NROI * CI + (size_t)r * CI + j];
        s += fmaxf(v, 0.0f);
    }
    s *= 0.125f;
    d_snb[(b * 4 + nb) * CI + j] = s;
    if (nb >= 2) {
        d_objf[(b * 2 + nb - 2) * CI + j] = s;   // argsort identity: cats never 0
        if (j == 0) out_labels[b * 2 + (nb - 2)] = (float)cat[b * 4 + 2 + (nb - 2)];
    }
}

// ============================================================
// K7: fused small dense heads (two independent GEMMs per stage)
// a1mode=1: path-1 A rows are mean of 4 consecutive d_snb rows (pooled)
// ============================================================
__global__ __launch_bounds__(256) void small_mm2(
    const float* __restrict__ A0, const float* __restrict__ B0,
    const float* __restrict__ bias0, float* __restrict__ C0, int rows0, int N0,
    const float* __restrict__ A1, const float* __restrict__ B1,
    const float* __restrict__ bias1, float* __restrict__ C1, int N1,
    int a1mode)
{
    __shared__ float As[512];
    __shared__ float red[256];
    const float *A, *Bm, *bias; float* C; int m, N; int mode = 0;
    if ((int)blockIdx.x < rows0) { A = A0; Bm = B0; bias = bias0; C = C0; m = blockIdx.x; N = N0; }
    else { A = A1; Bm = B1; bias = bias1; C = C1; m = blockIdx.x - rows0; N = N1; mode = a1mode; }
    int j0 = blockIdx.y * 64;
    if (j0 >= N) return;
    int tid = threadIdx.x, jl = tid & 63, ks = tid >> 6;
    if (mode) {
        for (int k = tid; k < 512; k += 256)
            As[k] = 0.25f * (A[(m * 4 + 0) * 512 + k] + A[(m * 4 + 1) * 512 + k] +
                             A[(m * 4 + 2) * 512 + k] + A[(m * 4 + 3) * 512 + k]);
    } else {
        for (int k = tid; k < 512; k += 256) As[k] = A[m * 512 + k];
    }
    __syncthreads();
    int j = j0 + jl;
    float acc = 0.0f;
    if (j < N) {
        int k0 = ks * 128;
#pragma unroll 8
        for (int k = k0; k < k0 + 128; ++k) acc += As[k] * Bm[k * N + j];
    }
    red[tid] = acc;
    __syncthreads();
    if (tid < 64 && j < N)
        C[m * N + j] = red[tid] + red[tid + 64] + red[tid + 128] + red[tid + 192] + bias[j];
}

// ============================================================
extern "C" void kernel_launch(void* const* d_in, const int* in_sizes, int n_in,
                              void* d_out, int out_size) {
    const float* x       = (const float*)d_in[0];
    const float* boxes   = (const float*)d_in[1];
    const int*   cat     = (const int*)d_in[2];
    const float* conv5_w = (const float*)d_in[3];
    const float* re_w    = (const float*)d_in[4];
    const float* re_b    = (const float*)d_in[5];
    const float* oc1_w   = (const float*)d_in[6];
    const float* oc1_b   = (const float*)d_in[7];
    const float* oc2_w   = (const float*)d_in[8];
    const float* oc2_b   = (const float*)d_in[9];
    const float* pr1_w   = (const float*)d_in[10];
    const float* pr1_b   = (const float*)d_in[11];
    const float* pr2_w   = (const float*)d_in[12];
    const float* pr2_b   = (const float*)d_in[13];

    float* out     = (float*)d_out;
    float* cls_out = out;                       // 16*174
    float* obj_cls = out + 16 * 174;            // 32*301
    float* labels  = out + 16 * 174 + 32 * 301; // 32

    float *p_objf, *p_snb, *p_h1, *p_g1;
    cudaGetSymbolAddress((void**)&p_objf, d_objf);
    cudaGetSymbolAddress((void**)&p_snb,  d_snb);
    cudaGetSymbolAddress((void**)&p_h1,   d_h1);
    cudaGetSymbolAddress((void**)&p_g1,   d_g1);

    cudaFuncSetAttribute(pool_kernel, cudaFuncAttributeMaxDynamicSharedMemorySize, POOL_SMEM);
    cudaFuncSetAttribute(gemm1k, cudaFuncAttributeMaxDynamicSharedMemorySize, GSMEM_BYTES);
    cudaFuncSetAttribute(gemm2k, cudaFuncAttributeMaxDynamicSharedMemorySize, GSMEM_BYTES);

    prep_kernel<<<PREP_BT + PREP_CW + PREP_CRW, 256>>>(boxes, conv5_w, re_w);
    pool_kernel<<<dim3(CIN / (32 * PCHUNKS), B_ * T_), 288, POOL_SMEM>>>(x);
    gemm1k<<<dim3(CI / 128, M1 / 64), 256, GSMEM_BYTES>>>();
    gemm2k<<<dim3(CI / 128, NROI / 64, NPART), 256, GSMEM_BYTES>>>();
    reduce_a<<<dim3(16, 4), 512>>>(re_b, cat, labels);
    // stage 1: h1 = objf@oc1 ; g1 = pooled@pr1 (pooled computed inline from snb)
    small_mm2<<<dim3(48, 8), 256>>>(p_objf, oc1_w, oc1_b, p_h1, 32, 512,
                                    p_snb, pr1_w, pr1_b, p_g1, 512, 1);
    // stage 2: obj_cls = h1@oc2 ; cls_out = g1@pr2
    small_mm2<<<dim3(48, 5), 256>>>(p_h1, oc2_w, oc2_b, obj_cls, 32, 301,
                                    p_g1, pr2_w, pr2_b, cls_out, 174, 0);
}

// round 16
// speedup vs baseline: 1.0167x; 1.0167x over previous
#include <cuda_runtime.h>
#include <cuda_fp16.h>
#include <cstdint>

// ---------------- problem constants ----------------
#define B_    16
#define T_    8
#define CIN   2048
#define CI    512
#define HF    14
#define HW    196
#define NROI  512
#define M1    4608          // NROI*9
#define KFEAT 4608          // CI*9
#define NPART 8             // split-K parts for gemm2

// ---------------- scratch (static device memory) ----------------
__device__ __half d_roisH[(size_t)M1 * CIN];
__device__ __half d_wH[(size_t)CI * CIN];
__device__ __half d_rwH[(size_t)CI * KFEAT];       // re_w transposed+permuted [n][bin*512+o]
__device__ __half d_featsH[(size_t)NROI * KFEAT];  // [roi][bin*512+o]
__device__ float d_regpart[(size_t)NPART * NROI * CI];
__device__ float d_snb[64 * CI];
__device__ float d_objf[32 * CI];
__device__ float d_h1[32 * CI];
__device__ float d_g1[16 * CI];
__device__ int2  d_tap[NROI * 9 * 16];   // {byte-offset into 197-float row, weight bits}

// ---------------- PTX helpers ----------------
__device__ __forceinline__ uint32_t sm_u32(const void* p) {
    return (uint32_t)__cvta_generic_to_shared(p);
}
__device__ __forceinline__ void cpa16(uint32_t dst, const void* src) {
    asm volatile("cp.async.cg.shared.global [%0], [%1], 16;\n" :: "r"(dst), "l"(src));
}
__device__ __forceinline__ void cpa_commit() {
    asm volatile("cp.async.commit_group;\n" ::: "memory");
}
__device__ __forceinline__ void cpa_wait3() {
    asm volatile("cp.async.wait_group 3;\n" ::: "memory");
}
__device__ __forceinline__ void ldsm4(uint32_t* r, uint32_t addr) {
    asm volatile("ldmatrix.sync.aligned.m8n8.x4.shared.b16 {%0,%1,%2,%3}, [%4];"
                 : "=r"(r[0]), "=r"(r[1]), "=r"(r[2]), "=r"(r[3]) : "r"(addr));
}
__device__ __forceinline__ void mma16816h(float* c, const uint32_t* a, uint32_t b0, uint32_t b1) {
    asm volatile("mma.sync.aligned.m16n8k16.row.col.f32.f16.f16.f32 "
                 "{%0,%1,%2,%3},{%4,%5,%6,%7},{%8,%9},{%0,%1,%2,%3};"
                 : "+f"(c[0]), "+f"(c[1]), "+f"(c[2]), "+f"(c[3])
                 : "r"(a[0]), "r"(a[1]), "r"(a[2]), "r"(a[3]), "r"(b0), "r"(b1));
}

// ============================================================
// K0: merged prep: [0] build_table (2), convw (4096), convrw (2304)
// ============================================================
#define PREP_BT   2
#define PREP_CW   (CI * CIN / 256)          // 4096
#define PREP_CRW  (16 * 16 * 9)             // 2304
__global__ __launch_bounds__(256) void prep_kernel(
    const float* __restrict__ boxes,
    const float* __restrict__ conv5_w,
    const float* __restrict__ re_w)
{
    int bid = blockIdx.x;
    if (bid < PREP_BT) {
        int roi = bid * 256 + threadIdx.x;
        if (roi >= NROI) return;
        float cx = boxes[roi * 4 + 0], cy = boxes[roi * 4 + 1];
        float w  = boxes[roi * 4 + 2], h  = boxes[roi * 4 + 3];
        const float s = 14.0f / 224.0f;
        float x1 = (cx - 0.5f * w) * 224.0f * s;
        float y1 = (cy - 0.5f * h) * 224.0f * s;
        float x2 = (cx + 0.5f * w) * 224.0f * s;
        float y2 = (cy + 0.5f * h) * 224.0f * s;
        float rw = fmaxf(x2 - x1, 1.0f), rh = fmaxf(y2 - y1, 1.0f);
        float bw = rw / 3.0f, bh = rh / 3.0f;
        float ys[6], xs[6];
#pragma unroll
        for (int p = 0; p < 3; ++p)
#pragma unroll
            for (int i = 0; i < 2; ++i) {
                ys[p * 2 + i] = y1 + p * bh + (i + 0.5f) * bh * 0.5f;
                xs[p * 2 + i] = x1 + p * bw + (i + 0.5f) * bw * 0.5f;
            }
#pragma unroll
        for (int ph = 0; ph < 3; ++ph)
#pragma unroll
            for (int pw = 0; pw < 3; ++pw) {
                int bin = ph * 3 + pw;
#pragma unroll
                for (int iy = 0; iy < 2; ++iy)
#pragma unroll
                    for (int ix = 0; ix < 2; ++ix) {
                        int smp = iy * 2 + ix;
                        float yy = ys[ph * 2 + iy];
                        float xx = xs[pw * 2 + ix];
                        bool valid = (yy > -1.0f) && (yy < 14.0f) && (xx > -1.0f) && (xx < 14.0f);
                        float y = fminf(fmaxf(yy, 0.0f), 13.0f);
                        float x = fminf(fmaxf(xx, 0.0f), 13.0f);
                        int y0 = (int)floorf(y), x0 = (int)floorf(x);
                        int y1i = min(y0 + 1, 13), x1i = min(x0 + 1, 13);
                        float ly = y - (float)y0, lx = x - (float)x0;
                        float hy = 1.0f - ly, hx = 1.0f - lx;
                        float q = valid ? 0.25f : 0.0f;
                        int base = (roi * 9 + bin) * 16 + smp * 4;
                        d_tap[base + 0] = make_int2((y0 * HF + x0) * 4,   __float_as_int(hy * hx * q));
                        d_tap[base + 1] = make_int2((y0 * HF + x1i) * 4,  __float_as_int(hy * lx * q));
                        d_tap[base + 2] = make_int2((y1i * HF + x0) * 4,  __float_as_int(ly * hx * q));
                        d_tap[base + 3] = make_int2((y1i * HF + x1i) * 4, __float_as_int(ly * lx * q));
                    }
            }
    } else if (bid < PREP_BT + PREP_CW) {
        int i = (bid - PREP_BT) * 256 + threadIdx.x;
        d_wH[i] = __float2half_rn(conv5_w[i]);
    } else {
        __shared__ float t[32][33];
        int cb = bid - PREP_BT - PREP_CW;
        int bin = cb / 256;
        int rem = cb - bin * 256;
        int o0 = (rem >> 4) * 32, n0 = (rem & 15) * 32;
        int tx = threadIdx.x & 31, ty = threadIdx.x >> 5;
        for (int r = ty; r < 32; r += 8)
            t[r][tx] = re_w[((size_t)((o0 + r) * 9 + bin)) * 512 + n0 + tx];
        __syncthreads();
        for (int r = ty; r < 32; r += 8) {
            size_t off = (size_t)(n0 + r) * KFEAT + bin * 512 + o0 + tx;
            d_rwH[off] = __float2half_rn(t[tx][r]);
        }
    }
}

// ============================================================
// K2: pooling in 2048-ch space -> fp16
// 4 chunks of 32 channels per block (R14 proven grid shape),
// 2 smem buffers (dynamic), register-staged LDG double-buffering,
// int4 (2-tap) LDS.128 tap loads
// ============================================================
#define PCHUNKS 4
#define PLDG    6
#define PBUF_E  (32 * 197)
#define POOL_SMEM (2 * PBUF_E * 4 + 576 * 8)
__global__ __launch_bounds__(288) void pool_kernel(const float* __restrict__ x) {
    extern __shared__ float psm[];
    float* pl0 = psm;
    float* pl1 = psm + PBUF_E;
    int2*  taps = (int2*)(psm + 2 * PBUF_E);

    int bt = blockIdx.y;
    int tid = threadIdx.x, lane = tid & 31, wid = tid >> 5;
    int cbase = blockIdx.x * (32 * PCHUNKS);

    size_t xbase = ((size_t)(bt >> 3) * CIN + cbase) * (size_t)(T_ * HW) + (size_t)(bt & 7) * HW;

    for (int i = tid; i < 576; i += 288) taps[i] = d_tap[bt * 576 + i];

    float4 v[PLDG];
    auto ldgc = [&](int c) {
#pragma unroll
        for (int q = 0; q < PLDG; ++q) {
            int i = tid + q * 288;
            if (i < 1568) {
                int ch = i / 49, p = i - ch * 49;
                v[q] = *(const float4*)(x + xbase + (size_t)(c * 32 + ch) * (T_ * HW) + p * 4);
            }
        }
    };
    auto stsc = [&](float* buf) {
#pragma unroll
        for (int q = 0; q < PLDG; ++q) {
            int i = tid + q * 288;
            if (i < 1568) {
                int ch = i / 49, p = i - ch * 49;
                float* d = buf + ch * 197 + p * 4;
                d[0] = v[q].x; d[1] = v[q].y; d[2] = v[q].z; d[3] = v[q].w;
            }
        }
    };

    ldgc(0);
    stsc(pl0);
    __syncthreads();

#pragma unroll
    for (int c = 0; c < PCHUNKS; ++c) {
        if (c + 1 < PCHUNKS) ldgc(c + 1);

        const char* bp = (const char*)((c & 1) ? (pl1 + lane * 197) : (pl0 + lane * 197));
#pragma unroll
        for (int j = 0; j < 4; ++j) {
            int e = wid + 9 * j;
            const int4* tp4 = (const int4*)&taps[e * 16];   // 2 taps per LDS.128
            float a = 0.0f;
#pragma unroll
            for (int t = 0; t < 8; ++t) {
                int4 q = tp4[t];
                a += __int_as_float(q.y) * *(const float*)(bp + q.x);
                a += __int_as_float(q.w) * *(const float*)(bp + q.z);
            }
            size_t off = (size_t)(bt * 36 + e) * CIN + cbase + c * 32 + lane;
            d_roisH[off] = __float2half_rn(a);
        }

        if (c + 1 < PCHUNKS) {
            stsc(((c + 1) & 1) ? pl1 : pl0);
            __syncthreads();
        }
    }
}

// ============================================================
// GEMM core: 64x128 tile, 256 threads (8 warps, 2x4 grid, warp 32x32),
// single-pass fp16, 5-stage cp.async -> 2 CTAs/SM co-residency
// ============================================================
#define KT     32
#define SROW   40
#define AROWS  64
#define BROWS  128
#define STAGE_E ((AROWS + BROWS) * SROW)
#define NSTAGE 5
#define GSMEM_BYTES (NSTAGE * STAGE_E * 2)

__device__ __forceinline__ void gemm_core(
    const __half* __restrict__ gA, int lda,
    const __half* __restrict__ gB, int ldb,
    int bm, int bn, int kbase, int niter,
    __half* sm, float (&acc)[2][4][4])
{
    int tid = threadIdx.x, lane = tid & 31, wid = tid >> 5;
    int wm = wid >> 2, wn = wid & 3;

    auto ldg = [&](int t) {
        int s = t % NSTAGE;
        int k0 = kbase + t * KT;
        __half* base = sm + s * STAGE_E;
#pragma unroll
        for (int q = 0; q < 3; ++q) {
            int idx = tid + q * 256;
            int row = idx >> 2, c = idx & 3;
            __half* pd = base + row * SROW + c * 8;
            const __half* src = (row < AROWS)
                ? gA + (size_t)(bm + row) * lda + k0 + c * 8
                : gB + (size_t)(bn + row - AROWS) * ldb + k0 + c * 8;
            cpa16(sm_u32(pd), src);
        }
    };

    int ar  = wm * 32 + (lane & 15);
    int ac8 = (lane >> 4) * 8;
    int br  = wn * 32 + (lane & 7) + ((lane >> 4) << 3);
    int bc8 = ((lane >> 3) & 1) * 8;

#pragma unroll
    for (int s = 0; s < 4; ++s) {
        if (s < niter) ldg(s);
        cpa_commit();
    }

#pragma unroll 1
    for (int t = 0; t < niter; ++t) {
        cpa_wait3();
        __syncthreads();
        if (t + 4 < niter) ldg(t + 4);
        cpa_commit();

        __half* base = sm + (t % NSTAGE) * STAGE_E;
        const __half* pA = base;
        const __half* pB = base + AROWS * SROW;

        uint32_t ah[2][2][4], bh[2][2][4];
#pragma unroll
        for (int ks = 0; ks < 2; ++ks) {
#pragma unroll
            for (int mt = 0; mt < 2; ++mt)
                ldsm4(ah[ks][mt], sm_u32(pA + (ar + mt * 16) * SROW + ks * 16 + ac8));
#pragma unroll
            for (int bt2 = 0; bt2 < 2; ++bt2)
                ldsm4(bh[ks][bt2], sm_u32(pB + (br + bt2 * 16) * SROW + ks * 16 + bc8));
        }
#pragma unroll
        for (int ks = 0; ks < 2; ++ks)
#pragma unroll
            for (int mt = 0; mt < 2; ++mt)
#pragma unroll
                for (int nt = 0; nt < 4; ++nt)
                    mma16816h(acc[mt][nt], ah[ks][mt],
                              bh[ks][nt >> 1][(nt & 1) * 2], bh[ks][nt >> 1][(nt & 1) * 2 + 1]);
    }
}

// ============================================================
// K4: GEMM1: feats = rois2048[4608,2048] x conv5_w[512,2048]^T
// ============================================================
__global__ __launch_bounds__(256) void gemm1k() {
    extern __shared__ __half sm[];
    int bm = blockIdx.y * 64, bn = blockIdx.x * 128;
    float acc[2][4][4];
#pragma unroll
    for (int a = 0; a < 2; ++a)
#pragma unroll
        for (int b = 0; b < 4; ++b)
#pragma unroll
            for (int c = 0; c < 4; ++c) acc[a][b][c] = 0.0f;

    gemm_core(d_roisH, CIN, d_wH, CIN, bm, bn, 0, CIN / KT, sm, acc);

    int lane = threadIdx.x & 31, wid = threadIdx.x >> 5;
    int wm = wid >> 2, wn = wid & 3;
    int mrow = wm * 32 + (lane >> 2);
    int ncol = wn * 32 + ((lane & 3) << 1);
#pragma unroll
    for (int mt = 0; mt < 2; ++mt)
#pragma unroll
        for (int nt = 0; nt < 4; ++nt) {
            float* c = acc[mt][nt];
            int n = bn + ncol + nt * 8;
#pragma unroll
            for (int half = 0; half < 2; ++half) {
                int m = bm + mrow + mt * 16 + half * 8;
                int roi = m / 9, bin = m - roi * 9;
                size_t off = (size_t)roi * KFEAT + bin * 512 + n;
                __half2 hp;
                hp.x = __float2half_rn(c[half * 2 + 0]);
                hp.y = __float2half_rn(c[half * 2 + 1]);
                *(__half2*)&d_featsH[off] = hp;
            }
        }
}

// ============================================================
// K5: GEMM2 (split-K=8): regpart = feats[512,4608] x rw[512,4608]^T
// ============================================================
__global__ __launch_bounds__(256) void gemm2k() {
    extern __shared__ __half sm[];
    int bm = blockIdx.y * 64, bn = blockIdx.x * 128;
    int part = blockIdx.z;
    float acc[2][4][4];
#pragma unroll
    for (int a = 0; a < 2; ++a)
#pragma unroll
        for (int b = 0; b < 4; ++b)
#pragma unroll
            for (int c = 0; c < 4; ++c) acc[a][b][c] = 0.0f;

    gemm_core(d_featsH, KFEAT, d_rwH, KFEAT,
              bm, bn, part * (KFEAT / NPART), (KFEAT / NPART) / KT, sm, acc);

    int lane = threadIdx.x & 31, wid = threadIdx.x >> 5;
    int wm = wid >> 2, wn = wid & 3;
    int mrow = wm * 32 + (lane >> 2);
    int ncol = wn * 32 + ((lane & 3) << 1);
    float* C = d_regpart + (size_t)part * NROI * CI;
#pragma unroll
    for (int mt = 0; mt < 2; ++mt)
#pragma unroll
        for (int nt = 0; nt < 4; ++nt) {
            float* c = acc[mt][nt];
            int n = bn + ncol + nt * 8;
#pragma unroll
            for (int half = 0; half < 2; ++half) {
                int m = bm + mrow + mt * 16 + half * 8;
                *(float2*)&C[(size_t)m * CI + n] = make_float2(c[half * 2], c[half * 2 + 1]);
            }
        }
}

// ============================================================
// K6: per-(b,nb): s = 0.125 * sum_t relu(bias + sum_p parts); labels
// ============================================================
__global__ void reduce_a(const float* __restrict__ re_b,
                         const int* __restrict__ cat,
                         float* __restrict__ out_labels) {
    int b = blockIdx.x, nb = blockIdx.y, j = threadIdx.x;
    float bias = re_b[j];
    float s = 0.0f;
#pragma unroll
    for (int t = 0; t < 8; ++t) {
        int r = (b * 8 + t) * 4 + nb;
        float v = bias;
#pragma unroll
        for (int p = 0; p < NPART; ++p)
            v += d_regpart[(size_t)p * NROI * CI + (size_t)r * CI + j];
        s += fmaxf(v, 0.0f);
    }
    s *= 0.125f;
    d_snb[(b * 4 + nb) * CI + j] = s;
    if (nb >= 2) {
        d_objf[(b * 2 + nb - 2) * CI + j] = s;   // argsort identity: cats never 0
        if (j == 0) out_labels[b * 2 + (nb - 2)] = (float)cat[b * 4 + 2 + (nb - 2)];
    }
}

// ============================================================
// K7: fused small dense heads (two independent GEMMs per stage)
// a1mode=1: path-1 A rows are mean of 4 consecutive d_snb rows (pooled)
// ============================================================
__global__ __launch_bounds__(256) void small_mm2(
    const float* __restrict__ A0, const float* __restrict__ B0,
    const float* __restrict__ bias0, float* __restrict__ C0, int rows0, int N0,
    const float* __restrict__ A1, const float* __restrict__ B1,
    const float* __restrict__ bias1, float* __restrict__ C1, int N1,
    int a1mode)
{
    __shared__ float As[512];
    __shared__ float red[256];
    const float *A, *Bm, *bias; float* C; int m, N; int mode = 0;
    if ((int)blockIdx.x < rows0) { A = A0; Bm = B0; bias = bias0; C = C0; m = blockIdx.x; N = N0; }
    else { A = A1; Bm = B1; bias = bias1; C = C1; m = blockIdx.x - rows0; N = N1; mode = a1mode; }
    int j0 = blockIdx.y * 64;
    if (j0 >= N) return;
    int tid = threadIdx.x, jl = tid & 63, ks = tid >> 6;
    if (mode) {
        for (int k = tid; k < 512; k += 256)
            As[k] = 0.25f * (A[(m * 4 + 0) * 512 + k] + A[(m * 4 + 1) * 512 + k] +
                             A[(m * 4 + 2) * 512 + k] + A[(m * 4 + 3) * 512 + k]);
    } else {
        for (int k = tid; k < 512; k += 256) As[k] = A[m * 512 + k];
    }
    __syncthreads();
    int j = j0 + jl;
    float acc = 0.0f;
    if (j < N) {
        int k0 = ks * 128;
#pragma unroll 8
        for (int k = k0; k < k0 + 128; ++k) acc += As[k] * Bm[k * N + j];
    }
    red[tid] = acc;
    __syncthreads();
    if (tid < 64 && j < N)
        C[m * N + j] = red[tid] + red[tid + 64] + red[tid + 128] + red[tid + 192] + bias[j];
}

// ============================================================
extern "C" void kernel_launch(void* const* d_in, const int* in_sizes, int n_in,
                              void* d_out, int out_size) {
    const float* x       = (const float*)d_in[0];
    const float* boxes   = (const float*)d_in[1];
    const int*   cat     = (const int*)d_in[2];
    const float* conv5_w = (const float*)d_in[3];
    const float* re_w    = (const float*)d_in[4];
    const float* re_b    = (const float*)d_in[5];
    const float* oc1_w   = (const float*)d_in[6];
    const float* oc1_b   = (const float*)d_in[7];
    const float* oc2_w   = (const float*)d_in[8];
    const float* oc2_b   = (const float*)d_in[9];
    const float* pr1_w   = (const float*)d_in[10];
    const float* pr1_b   = (const float*)d_in[11];
    const float* pr2_w   = (const float*)d_in[12];
    const float* pr2_b   = (const float*)d_in[13];

    float* out     = (float*)d_out;
    float* cls_out = out;                       // 16*174
    float* obj_cls = out + 16 * 174;            // 32*301
    float* labels  = out + 16 * 174 + 32 * 301; // 32

    float *p_objf, *p_snb, *p_h1, *p_g1;
    cudaGetSymbolAddress((void**)&p_objf, d_objf);
    cudaGetSymbolAddress((void**)&p_snb,  d_snb);
    cudaGetSymbolAddress((void**)&p_h1,   d_h1);
    cudaGetSymbolAddress((void**)&p_g1,   d_g1);

    cudaFuncSetAttribute(pool_kernel, cudaFuncAttributeMaxDynamicSharedMemorySize, POOL_SMEM);
    cudaFuncSetAttribute(gemm1k, cudaFuncAttributeMaxDynamicSharedMemorySize, GSMEM_BYTES);
    cudaFuncSetAttribute(gemm2k, cudaFuncAttributeMaxDynamicSharedMemorySize, GSMEM_BYTES);

    prep_kernel<<<PREP_BT + PREP_CW + PREP_CRW, 256>>>(boxes, conv5_w, re_w);
    pool_kernel<<<dim3(CIN / (32 * PCHUNKS), B_ * T_), 288, POOL_SMEM>>>(x);
    gemm1k<<<dim3(CI / 128, M1 / 64), 256, GSMEM_BYTES>>>();
    gemm2k<<<dim3(CI / 128, NROI / 64, NPART), 256, GSMEM_BYTES>>>();
    reduce_a<<<dim3(16, 4), 512>>>(re_b, cat, labels);
    // stage 1: h1 = objf@oc1 ; g1 = pooled@pr1 (pooled computed inline from snb)
    small_mm2<<<dim3(48, 8), 256>>>(p_objf, oc1_w, oc1_b, p_h1, 32, 512,
                                    p_snb, pr1_w, pr1_b, p_g1, 512, 1);
    // stage 2: obj_cls = h1@oc2 ; cls_out = g1@pr2
    small_mm2<<<dim3(48, 5), 256>>>(p_h1, oc2_w, oc2_b, obj_cls, 32, 301,
                                    p_g1, pr2_w, pr2_b, cls_out, 174, 0);
}